// round 5
// baseline (speedup 1.0000x reference)
#include <cuda_runtime.h>
#include <cstdint>

// B=8, C=4, H=W=1024, PATCH=16, DOWN=4 -> L=4096 (64x64 patches), M=L2=256.
// att_gt[b,c,l,m] = (1/4096) * sum_{k in [0,256): class(b,l,k)==c} cnt[b,c, pix(m,k)]
//   cnt = #pixels of class c in the 4x4 pool block (0..16), pix(m,k) = pooled
//   pixel (my*16+ky, mx*16+kx) with m=(my,mx), k=(ky,kx).
// Loss = mean over 33,554,432 elements of (att - att_gt)^2.
// NOTE: target is int32 on disk (JAX x64-disabled downgrades the int64 request).

// ---------------- device scratch (no allocation allowed) ----------------
static __device__ uint8_t  g_V[8u * 4u * 256u * 256u];   // [b][c][k][m] counts 0..16
static __device__ uint8_t  g_list[8u * 4096u * 256u];    // [b][l][256] k's sorted by class
static __device__ ushort4  g_cnt[8u * 4096u];            // [b][l] per-class counts
static __device__ double   g_part[256];                  // per-block partial sums

// ---------------- kernel 1: pooled class counts -> V[b][c][k][m] --------
__global__ void k_pool(const int* __restrict__ tgt) {
    int t = blockIdx.x * 256 + threadIdx.x;          // 524288 threads: (b, Y, X)
    int b = t >> 16, Y = (t >> 8) & 255, X = t & 255;
    const int* p = tgt + ((size_t)b << 20) + (size_t)(Y * 4) * 1024 + X * 4;
    int c0 = 0, c1 = 0, c2 = 0, c3 = 0;
#pragma unroll
    for (int dy = 0; dy < 4; dy++) {
        int4 q = *reinterpret_cast<const int4*>(p + (size_t)dy * 1024);
        c0 += (q.x == 0); c1 += (q.x == 1); c2 += (q.x == 2); c3 += (q.x == 3);
        c0 += (q.y == 0); c1 += (q.y == 1); c2 += (q.y == 2); c3 += (q.y == 3);
        c0 += (q.z == 0); c1 += (q.z == 1); c2 += (q.z == 2); c3 += (q.z == 3);
        c0 += (q.w == 0); c1 += (q.w == 1); c2 += (q.w == 2); c3 += (q.w == 3);
    }
    int m = ((Y >> 4) << 4) + (X >> 4);              // pooled-map patch index
    int k = ((Y & 15) << 4) + (X & 15);              // kernel position in patch
    size_t base = (size_t)b * 262144 + (size_t)k * 256 + m;
    g_V[base         ] = (uint8_t)c0;
    g_V[base +  65536] = (uint8_t)c1;
    g_V[base + 131072] = (uint8_t)c2;
    g_V[base + 196608] = (uint8_t)c3;
}

// ---------------- kernel 2: per-(b,l) counting sort of k by class -------
__global__ void k_lists(const int* __restrict__ tgt) {
    __shared__ uint8_t sc[8 * 256];
    int warp = threadIdx.x >> 5, lane = threadIdx.x & 31;
    int gw = blockIdx.x * 8 + warp;                  // 0..32767 = b*4096 + l
    int b = gw >> 12, l = gw & 4095;
    int py = l >> 6, px = l & 63;
    {
        int ky = lane >> 1, kx0 = (lane & 1) * 8;
        const int* p = tgt + ((size_t)b << 20)
                     + (size_t)(py * 16 + ky) * 1024 + px * 16 + kx0;
        int4 q0 = *reinterpret_cast<const int4*>(p);
        int4 q1 = *reinterpret_cast<const int4*>(p + 4);
        uint8_t* dst = sc + warp * 256 + ky * 16 + kx0;
        dst[0] = (uint8_t)q0.x; dst[1] = (uint8_t)q0.y;
        dst[2] = (uint8_t)q0.z; dst[3] = (uint8_t)q0.w;
        dst[4] = (uint8_t)q1.x; dst[5] = (uint8_t)q1.y;
        dst[6] = (uint8_t)q1.z; dst[7] = (uint8_t)q1.w;
    }
    __syncwarp();
    const uint8_t* cw = sc + warp * 256;
    int t0 = 0, t1 = 0, t2 = 0, t3 = 0;
#pragma unroll
    for (int r = 0; r < 8; r++) {
        int c = cw[r * 32 + lane];
        t0 += __popc(__ballot_sync(0xffffffffu, c == 0));
        t1 += __popc(__ballot_sync(0xffffffffu, c == 1));
        t2 += __popc(__ballot_sync(0xffffffffu, c == 2));
        t3 += __popc(__ballot_sync(0xffffffffu, c == 3));
    }
    int b0 = 0, b1 = t0, b2 = t0 + t1, b3 = t0 + t1 + t2;
    size_t lbase = (size_t)b * 4096 + l;
    uint8_t* out = g_list + lbase * 256;
    unsigned lt = (1u << lane) - 1u;
#pragma unroll
    for (int r = 0; r < 8; r++) {
        int k = r * 32 + lane;
        int c = cw[k];
        unsigned m0 = __ballot_sync(0xffffffffu, c == 0);
        unsigned m1 = __ballot_sync(0xffffffffu, c == 1);
        unsigned m2 = __ballot_sync(0xffffffffu, c == 2);
        unsigned m3 = __ballot_sync(0xffffffffu, c == 3);
        int pos = (c == 0) ? b0 + __popc(m0 & lt)
                : (c == 1) ? b1 + __popc(m1 & lt)
                : (c == 2) ? b2 + __popc(m2 & lt)
                :            b3 + __popc(m3 & lt);
        out[pos] = (uint8_t)k;
        b0 += __popc(m0); b1 += __popc(m1); b2 += __popc(m2); b3 += __popc(m3);
    }
    if (lane == 0)
        g_cnt[lbase] = make_ushort4((unsigned short)t0, (unsigned short)t1,
                                    (unsigned short)t2, (unsigned short)t3);
}

// ---------------- kernel 3: main accumulation + fused MSE ----------------
// grid (lg=8, c=4, b=8) = 256 blocks, 256 threads (8 warps). Each block:
// smem V slab for (b,c): 256k x 256m u8 = 64KB. Warp owns one l per iter;
// lane owns m = lane*8..lane*8+7 as 4 u32 accumulators of 2x u16 lanes.
__global__ void __launch_bounds__(256, 1) k_main(const float* __restrict__ att) {
    extern __shared__ uint8_t sm[];
    uint8_t* Vs = sm;                       // 65536 B
    uint8_t* Ls = sm + 65536;               // 8 warps * 256 B
    double*  wsum = (double*)(sm + 65536 + 2048);
    int b = blockIdx.z, c = blockIdx.y, lg = blockIdx.x;

    {   // load V slab (coalesced uint4)
        const uint4* src = (const uint4*)(g_V + (((size_t)b * 4 + c) << 16));
        uint4* dst = (uint4*)Vs;
        for (int i = threadIdx.x; i < 4096; i += 256) dst[i] = src[i];
    }
    __syncthreads();

    int warp = threadIdx.x >> 5, lane = threadIdx.x & 31;
    uint8_t* lw = Ls + warp * 256;
    const float inv = 1.0f / 4096.0f;
    float s = 0.0f;

    for (int li = 0; li < 64; li++) {
        int l = (lg << 9) + (li << 3) + warp;
        size_t lbase = (size_t)b * 4096 + l;
        __syncwarp();
        ((uint64_t*)lw)[lane] = ((const uint64_t*)g_list)[lbase * 32 + lane];
        __syncwarp();
        ushort4 cn = g_cnt[lbase];
        int start = (c > 0 ? (int)cn.x : 0) + (c > 1 ? (int)cn.y : 0)
                  + (c > 2 ? (int)cn.z : 0);
        int n = (c == 0) ? (int)cn.x : (c == 1) ? (int)cn.y
              : (c == 2) ? (int)cn.z : (int)cn.w;

        uint32_t a0 = 0, a1 = 0, a2 = 0, a3 = 0;
        const uint8_t* lp = lw + start;
        int i = 0;
        for (; i + 4 <= n; i += 4) {
            int k0 = lp[i], k1 = lp[i + 1], k2 = lp[i + 2], k3 = lp[i + 3];
            uint2 v0 = *(const uint2*)(Vs + (k0 << 8) + (lane << 3));
            uint2 v1 = *(const uint2*)(Vs + (k1 << 8) + (lane << 3));
            uint2 v2 = *(const uint2*)(Vs + (k2 << 8) + (lane << 3));
            uint2 v3 = *(const uint2*)(Vs + (k3 << 8) + (lane << 3));
            a0 += __byte_perm(v0.x, 0, 0x4140); a1 += __byte_perm(v0.x, 0, 0x4342);
            a2 += __byte_perm(v0.y, 0, 0x4140); a3 += __byte_perm(v0.y, 0, 0x4342);
            a0 += __byte_perm(v1.x, 0, 0x4140); a1 += __byte_perm(v1.x, 0, 0x4342);
            a2 += __byte_perm(v1.y, 0, 0x4140); a3 += __byte_perm(v1.y, 0, 0x4342);
            a0 += __byte_perm(v2.x, 0, 0x4140); a1 += __byte_perm(v2.x, 0, 0x4342);
            a2 += __byte_perm(v2.y, 0, 0x4140); a3 += __byte_perm(v2.y, 0, 0x4342);
            a0 += __byte_perm(v3.x, 0, 0x4140); a1 += __byte_perm(v3.x, 0, 0x4342);
            a2 += __byte_perm(v3.y, 0, 0x4140); a3 += __byte_perm(v3.y, 0, 0x4342);
        }
        for (; i < n; i++) {
            int k = lp[i];
            uint2 v = *(const uint2*)(Vs + (k << 8) + (lane << 3));
            a0 += __byte_perm(v.x, 0, 0x4140); a1 += __byte_perm(v.x, 0, 0x4342);
            a2 += __byte_perm(v.y, 0, 0x4140); a3 += __byte_perm(v.y, 0, 0x4342);
        }

        // fused MSE epilogue: att[b,c,l, lane*8 .. lane*8+7]
        const float4* ap = (const float4*)att
                         + (((size_t)(b * 4 + c) * 4096 + l) << 6) + (lane << 1);
        float4 q0 = __ldg(ap);
        float4 q1 = __ldg(ap + 1);
        float d;
        d = q0.x - (float)(a0 & 0xffffu) * inv; s += d * d;
        d = q0.y - (float)(a0 >> 16)    * inv; s += d * d;
        d = q0.z - (float)(a1 & 0xffffu) * inv; s += d * d;
        d = q0.w - (float)(a1 >> 16)    * inv; s += d * d;
        d = q1.x - (float)(a2 & 0xffffu) * inv; s += d * d;
        d = q1.y - (float)(a2 >> 16)    * inv; s += d * d;
        d = q1.z - (float)(a3 & 0xffffu) * inv; s += d * d;
        d = q1.w - (float)(a3 >> 16)    * inv; s += d * d;
    }

    // deterministic block reduction
#pragma unroll
    for (int o = 16; o > 0; o >>= 1) s += __shfl_down_sync(0xffffffffu, s, o);
    if (lane == 0) wsum[warp] = (double)s;
    __syncthreads();
    if (threadIdx.x == 0) {
        double t = 0.0;
#pragma unroll
        for (int w = 0; w < 8; w++) t += wsum[w];
        g_part[((size_t)blockIdx.z * 4 + blockIdx.y) * 8 + blockIdx.x] = t;
    }
}

// ---------------- kernel 4: final deterministic reduction ----------------
__global__ void k_final(float* __restrict__ out) {
    __shared__ double sh[256];
    int t = threadIdx.x;
    sh[t] = g_part[t];
    __syncthreads();
#pragma unroll
    for (int o = 128; o > 0; o >>= 1) {
        if (t < o) sh[t] += sh[t + o];
        __syncthreads();
    }
    if (t == 0) out[0] = (float)(sh[0] / 33554432.0);
}

// ---------------- launch -------------------------------------------------
extern "C" void kernel_launch(void* const* d_in, const int* in_sizes, int n_in,
                              void* d_out, int out_size) {
    (void)in_sizes; (void)n_in; (void)out_size;
    // d_in[0] = pred (unused), d_in[1] = target int32, d_in[2] = attentions f32
    const int*   tgt = (const int*)d_in[1];
    const float* att = (const float*)d_in[2];
    float*       out = (float*)d_out;

    const int MAIN_SMEM = 65536 + 2048 + 8 * (int)sizeof(double);
    cudaFuncSetAttribute(k_main, cudaFuncAttributeMaxDynamicSharedMemorySize,
                         MAIN_SMEM);

    k_pool<<<2048, 256>>>(tgt);
    k_lists<<<4096, 256>>>(tgt);
    k_main<<<dim3(8, 4, 8), 256, MAIN_SMEM>>>(att);
    k_final<<<1, 256>>>(out);
}

// round 6
// speedup vs baseline: 1.5746x; 1.5746x over previous
#include <cuda_runtime.h>
#include <cstdint>

// B=8, C=4, H=W=1024, PATCH=16, DOWN=4 -> L=4096 (64x64 patches), M=L2=256.
// att_gt[b,c,l,m] = (1/4096) * sum_{k in [0,256): class(b,l,k)==c} cnt[b,c, pix(m,k)]
//   cnt = #pixels of class c in the 4x4 pool block (0..16).
// Loss = mean over 33,554,432 elements of (att - att_gt)^2.
// target is int32 on disk (JAX x64-disabled downgrades the int64 request).

// ---------------- device scratch (no allocation allowed) ----------------
static __device__ __align__(16) uint8_t g_V[8u * 4u * 256u * 256u]; // [b][c][k][m]
static __device__ __align__(16) uint8_t g_list[8u * 4096u * 256u];  // [b][l][256] k's by class
static __device__ ushort4 g_cnt[8u * 4096u];                        // [b][l] class counts
static __device__ double  g_part[256];                              // per-block partials

// ---------------- kernel 1: pooled class counts -> V[b][c][k][m] --------
// block = one (b, Y) pooled row (256 threads = X). Staged smem -> uint4 stores.
__global__ void k_pool(const int* __restrict__ tgt) {
    __shared__ __align__(16) uint8_t stage[4][256];
    int X = threadIdx.x;
    int Y = blockIdx.x & 255, b = blockIdx.x >> 8;
    const int* p = tgt + ((size_t)b << 20) + (size_t)(Y * 4) * 1024 + X * 4;
    int c0 = 0, c1 = 0, c2 = 0, c3 = 0;
#pragma unroll
    for (int dy = 0; dy < 4; dy++) {
        int4 q = *reinterpret_cast<const int4*>(p + (size_t)dy * 1024);
        c0 += (q.x == 0); c1 += (q.x == 1); c2 += (q.x == 2); c3 += (q.x == 3);
        c0 += (q.y == 0); c1 += (q.y == 1); c2 += (q.y == 2); c3 += (q.y == 3);
        c0 += (q.z == 0); c1 += (q.z == 1); c2 += (q.z == 2); c3 += (q.z == 3);
        c0 += (q.w == 0); c1 += (q.w == 1); c2 += (q.w == 2); c3 += (q.w == 3);
    }
    int sidx = (X & 15) * 16 + (X >> 4);        // [i=k-offset][j=m-offset]
    stage[0][sidx] = (uint8_t)c0;
    stage[1][sidx] = (uint8_t)c1;
    stage[2][sidx] = (uint8_t)c2;
    stage[3][sidx] = (uint8_t)c3;
    __syncthreads();
    if (X < 64) {
        int c = X >> 4, i = X & 15;
        int kbase = (Y & 15) << 4, mbase = (Y >> 4) << 4;
        uint4 v = *reinterpret_cast<const uint4*>(&stage[c][i * 16]);
        *reinterpret_cast<uint4*>(g_V + (size_t)b * 262144 + (size_t)c * 65536
                                  + (size_t)(kbase + i) * 256 + mbase) = v;
    }
}

// ---------------- kernel 2: per-(b,l) counting sort of k by class -------
__global__ void k_lists(const int* __restrict__ tgt) {
    __shared__ uint8_t sc[8 * 256];
    int warp = threadIdx.x >> 5, lane = threadIdx.x & 31;
    int gw = blockIdx.x * 8 + warp;                  // 0..32767 = b*4096 + l
    int b = gw >> 12, l = gw & 4095;
    int py = l >> 6, px = l & 63;
    {
        int ky = lane >> 1, kx0 = (lane & 1) * 8;
        const int* p = tgt + ((size_t)b << 20)
                     + (size_t)(py * 16 + ky) * 1024 + px * 16 + kx0;
        int4 q0 = *reinterpret_cast<const int4*>(p);
        int4 q1 = *reinterpret_cast<const int4*>(p + 4);
        uint8_t* dst = sc + warp * 256 + ky * 16 + kx0;
        dst[0] = (uint8_t)q0.x; dst[1] = (uint8_t)q0.y;
        dst[2] = (uint8_t)q0.z; dst[3] = (uint8_t)q0.w;
        dst[4] = (uint8_t)q1.x; dst[5] = (uint8_t)q1.y;
        dst[6] = (uint8_t)q1.z; dst[7] = (uint8_t)q1.w;
    }
    __syncwarp();
    const uint8_t* cw = sc + warp * 256;
    int t0 = 0, t1 = 0, t2 = 0, t3 = 0;
#pragma unroll
    for (int r = 0; r < 8; r++) {
        int c = cw[r * 32 + lane];
        t0 += __popc(__ballot_sync(0xffffffffu, c == 0));
        t1 += __popc(__ballot_sync(0xffffffffu, c == 1));
        t2 += __popc(__ballot_sync(0xffffffffu, c == 2));
        t3 += __popc(__ballot_sync(0xffffffffu, c == 3));
    }
    int b0 = 0, b1 = t0, b2 = t0 + t1, b3 = t0 + t1 + t2;
    size_t lbase = (size_t)b * 4096 + l;
    uint8_t* out = g_list + lbase * 256;
    unsigned lt = (1u << lane) - 1u;
#pragma unroll
    for (int r = 0; r < 8; r++) {
        int k = r * 32 + lane;
        int c = cw[k];
        unsigned m0 = __ballot_sync(0xffffffffu, c == 0);
        unsigned m1 = __ballot_sync(0xffffffffu, c == 1);
        unsigned m2 = __ballot_sync(0xffffffffu, c == 2);
        unsigned m3 = __ballot_sync(0xffffffffu, c == 3);
        int pos = (c == 0) ? b0 + __popc(m0 & lt)
                : (c == 1) ? b1 + __popc(m1 & lt)
                : (c == 2) ? b2 + __popc(m2 & lt)
                :            b3 + __popc(m3 & lt);
        out[pos] = (uint8_t)k;
        b0 += __popc(m0); b1 += __popc(m1); b2 += __popc(m2); b3 += __popc(m3);
    }
    if (lane == 0)
        g_cnt[lbase] = make_ushort4((unsigned short)t0, (unsigned short)t1,
                                    (unsigned short)t2, (unsigned short)t3);
}

// ---------------- kernel 3: main accumulation + fused MSE ----------------
// grid (lg=8, c=4, b=8) = 256 blocks, 512 threads (16 warps). Each block:
// smem V slab for (b,c): 256k x 256m u8 = 64KB. Warp owns one l per iter;
// lane owns m = lane*8..lane*8+7. Inner loop: u32 index loads (4 sorted k's),
// exact u8-lane accumulation (cnt<=16, <=15 adds per flush window is safe;
// chains get <=8 adds -> <=128 < 255), flushed to u16 lanes via PRMT.
__global__ void __launch_bounds__(512, 2) k_main(const float* __restrict__ att) {
    extern __shared__ uint8_t sm[];
    uint8_t* Vs = sm;                        // 65536 B
    uint8_t* Ls = sm + 65536;                // 16 warps * 256 B
    double*  wsum = (double*)(sm + 65536 + 4096);
    int b = blockIdx.z, c = blockIdx.y, lg = blockIdx.x;

    {   // load V slab (coalesced uint4)
        const uint4* src = (const uint4*)(g_V + (((size_t)b * 4 + c) << 16));
        uint4* dst = (uint4*)Vs;
        for (int i = threadIdx.x; i < 4096; i += 512) dst[i] = src[i];
    }
    __syncthreads();

    int warp = threadIdx.x >> 5, lane = threadIdx.x & 31;
    uint8_t* lw = Ls + warp * 256;
    const uint8_t* Vb = Vs + (lane << 3);
    const float inv = 1.0f / 4096.0f;
    float s = 0.0f;

    for (int li = 0; li < 32; li++) {
        int l = (lg << 9) + (li << 4) + warp;
        size_t lbase = (size_t)b * 4096 + l;
        __syncwarp();
        ((uint64_t*)lw)[lane] = ((const uint64_t*)g_list)[lbase * 32 + lane];
        __syncwarp();
        ushort4 cn = g_cnt[lbase];
        int start = (c > 0 ? (int)cn.x : 0) + (c > 1 ? (int)cn.y : 0)
                  + (c > 2 ? (int)cn.z : 0);
        int n = (c == 0) ? (int)cn.x : (c == 1) ? (int)cn.y
              : (c == 2) ? (int)cn.z : (int)cn.w;

        uint32_t a0 = 0, a1 = 0, a2 = 0, a3 = 0;   // 2x u16 lanes each
        int p = start, e = start + n;

        // scalar head to 4-alignment (<=3 iters)
        while ((p & 3) && p < e) {
            int k = lw[p++];
            uint2 v = *(const uint2*)(Vb + (k << 8));
            a0 += __byte_perm(v.x, 0, 0x4140); a1 += __byte_perm(v.x, 0, 0x4342);
            a2 += __byte_perm(v.y, 0, 0x4140); a3 += __byte_perm(v.y, 0, 0x4342);
        }
        const uint32_t* wp = (const uint32_t*)lw;

        // 16-k superchunks: 4 u32 index loads, u8-lane accumulation, one flush
        while (e - p >= 16) {
            uint32_t b0 = 0, b1 = 0, b2 = 0, b3 = 0;
#pragma unroll
            for (int g = 0; g < 4; g++) {
                uint32_t i4 = wp[(p >> 2) + g];
                uint2 v0 = *(const uint2*)(Vb + ((i4 & 255u) << 8));
                uint2 v1 = *(const uint2*)(Vb + (((i4 >> 8) & 255u) << 8));
                uint2 v2 = *(const uint2*)(Vb + (((i4 >> 16) & 255u) << 8));
                uint2 v3 = *(const uint2*)(Vb + ((i4 >> 24) << 8));
                b0 += v0.x; b1 += v0.y;
                b2 += v1.x; b3 += v1.y;
                b0 += v2.x; b1 += v2.y;
                b2 += v3.x; b3 += v3.y;
            }
            a0 += __byte_perm(b0, 0, 0x4140); a1 += __byte_perm(b0, 0, 0x4342);
            a2 += __byte_perm(b1, 0, 0x4140); a3 += __byte_perm(b1, 0, 0x4342);
            a0 += __byte_perm(b2, 0, 0x4140); a1 += __byte_perm(b2, 0, 0x4342);
            a2 += __byte_perm(b3, 0, 0x4140); a3 += __byte_perm(b3, 0, 0x4342);
            p += 16;
        }
        // tail: <=15 k's total -> single u8-lane window then flush
        {
            uint32_t b0 = 0, b1 = 0;
            while (e - p >= 4) {
                uint32_t i4 = wp[p >> 2];
                uint2 v0 = *(const uint2*)(Vb + ((i4 & 255u) << 8));
                uint2 v1 = *(const uint2*)(Vb + (((i4 >> 8) & 255u) << 8));
                uint2 v2 = *(const uint2*)(Vb + (((i4 >> 16) & 255u) << 8));
                uint2 v3 = *(const uint2*)(Vb + ((i4 >> 24) << 8));
                b0 += v0.x; b1 += v0.y;
                b0 += v1.x; b1 += v1.y;
                b0 += v2.x; b1 += v2.y;
                b0 += v3.x; b1 += v3.y;
                p += 4;
            }
            while (p < e) {
                int k = lw[p++];
                uint2 v = *(const uint2*)(Vb + (k << 8));
                b0 += v.x; b1 += v.y;
            }
            a0 += __byte_perm(b0, 0, 0x4140); a1 += __byte_perm(b0, 0, 0x4342);
            a2 += __byte_perm(b1, 0, 0x4140); a3 += __byte_perm(b1, 0, 0x4342);
        }

        // fused MSE epilogue: att[b,c,l, lane*8 .. lane*8+7]
        const float4* ap = (const float4*)att
                         + (((size_t)(b * 4 + c) * 4096 + l) << 6) + (lane << 1);
        float4 q0 = __ldg(ap);
        float4 q1 = __ldg(ap + 1);
        float d;
        d = q0.x - (float)(a0 & 0xffffu) * inv; s += d * d;
        d = q0.y - (float)(a0 >> 16)     * inv; s += d * d;
        d = q0.z - (float)(a1 & 0xffffu) * inv; s += d * d;
        d = q0.w - (float)(a1 >> 16)     * inv; s += d * d;
        d = q1.x - (float)(a2 & 0xffffu) * inv; s += d * d;
        d = q1.y - (float)(a2 >> 16)     * inv; s += d * d;
        d = q1.z - (float)(a3 & 0xffffu) * inv; s += d * d;
        d = q1.w - (float)(a3 >> 16)     * inv; s += d * d;
    }

    // deterministic block reduction
#pragma unroll
    for (int o = 16; o > 0; o >>= 1) s += __shfl_down_sync(0xffffffffu, s, o);
    if (lane == 0) wsum[warp] = (double)s;
    __syncthreads();
    if (threadIdx.x == 0) {
        double t = 0.0;
#pragma unroll
        for (int w = 0; w < 16; w++) t += wsum[w];
        g_part[((size_t)blockIdx.z * 4 + blockIdx.y) * 8 + blockIdx.x] = t;
    }
}

// ---------------- kernel 4: final deterministic reduction ----------------
__global__ void k_final(float* __restrict__ out) {
    __shared__ double sh[256];
    int t = threadIdx.x;
    sh[t] = g_part[t];
    __syncthreads();
#pragma unroll
    for (int o = 128; o > 0; o >>= 1) {
        if (t < o) sh[t] += sh[t + o];
        __syncthreads();
    }
    if (t == 0) out[0] = (float)(sh[0] / 33554432.0);
}

// ---------------- launch -------------------------------------------------
extern "C" void kernel_launch(void* const* d_in, const int* in_sizes, int n_in,
                              void* d_out, int out_size) {
    (void)in_sizes; (void)n_in; (void)out_size;
    // d_in[0] = pred (unused), d_in[1] = target int32, d_in[2] = attentions f32
    const int*   tgt = (const int*)d_in[1];
    const float* att = (const float*)d_in[2];
    float*       out = (float*)d_out;

    const int MAIN_SMEM = 65536 + 4096 + 16 * (int)sizeof(double);
    cudaFuncSetAttribute(k_main, cudaFuncAttributeMaxDynamicSharedMemorySize,
                         MAIN_SMEM);

    k_pool<<<2048, 256>>>(tgt);
    k_lists<<<4096, 256>>>(tgt);
    k_main<<<dim3(8, 4, 8), 512, MAIN_SMEM>>>(att);
    k_final<<<1, 256>>>(out);
}